// round 3
// baseline (speedup 1.0000x reference)
#include <cuda_runtime.h>
#include <cstdint>

#define N_NODES 8192
#define N_EDGES 8192
#define DEG     32
#define NNZ     (N_EDGES * DEG)
#define D       32
#define MASK_WORDS_PER_ROW (N_EDGES / 32)            // 256
#define MASK_WORDS (N_NODES * MASK_WORDS_PER_ROW)    // 2M words = 8 MB

// Scratch (device globals; no allocation allowed)
__device__ float    g_c;
__device__ float    g_p[N_NODES * 2];   // p[n] = x_0[n] @ M (2 comps interleaved)
__device__ float    g_y[N_NODES * 2];   // y[n] = sum_{e∋n} z[e]
__device__ float    g_a[N_NODES];       // a[n] = sum_{e∋n} t[e].0
__device__ float    g_b[N_EDGES];       // b[e] = t[e].1
__device__ unsigned g_mask[MASK_WORDS]; // incidence bitmask, row-major

// ---------------------------------------------------------------------------
// Zero all accumulators + bitmask (one grid-stride-free pass, uint4 stores).
// ---------------------------------------------------------------------------
__global__ void k_init() {
    const int i = blockIdx.x * blockDim.x + threadIdx.x;   // 0 .. 512K-1
    const uint4 z4 = make_uint4(0u, 0u, 0u, 0u);
    if (i < MASK_WORDS / 4) ((uint4*)g_mask)[i] = z4;
    if (i < (N_NODES * 2) / 4) ((float4*)g_y)[i] = make_float4(0.f, 0.f, 0.f, 0.f);
    if (i < N_NODES / 4) ((float4*)g_a)[i] = make_float4(0.f, 0.f, 0.f, 0.f);
}

// ---------------------------------------------------------------------------
// Fused: fold affine chain into M (32x2) + c (redundantly per block), then
// p[n] = x_0[n] @ M.
//   q = Wm2@Wm3 ; [u|v] = split(Wm1@q) ; c = bm1·q + bm2·Wm3 + bm3
//   M = W_l1 @ [ (W_l2 u) | v ]
// ---------------------------------------------------------------------------
__global__ void k_p(const float* __restrict__ x0,
                    const float* __restrict__ Wl1, const float* __restrict__ Wl2,
                    const float* __restrict__ Wm1, const float* __restrict__ bm1,
                    const float* __restrict__ Wm2, const float* __restrict__ bm2,
                    const float* __restrict__ Wm3, const float* __restrict__ bm3) {
    __shared__ float q[D], u[D], v[D], w2u[D], M0[D], M1[D];
    const int t = threadIdx.x;
    if (t < D) {
        float s = 0.f;
        #pragma unroll
        for (int j = 0; j < D; ++j) s += Wm2[t * D + j] * Wm3[j];
        q[t] = s;
    }
    __syncthreads();
    if (t < D) {
        float su = 0.f, sv = 0.f;
        #pragma unroll
        for (int j = 0; j < D; ++j) {
            su += Wm1[t * D + j] * q[j];
            sv += Wm1[(D + t) * D + j] * q[j];
        }
        u[t] = su; v[t] = sv;
    }
    __syncthreads();
    if (t < D) {
        float s = 0.f;
        #pragma unroll
        for (int j = 0; j < D; ++j) s += Wl2[t * D + j] * u[j];
        w2u[t] = s;
    }
    if (blockIdx.x == 0 && t == 0) {
        float c = bm3[0];
        #pragma unroll
        for (int j = 0; j < D; ++j) c += bm1[j] * q[j] + bm2[j] * Wm3[j];
        g_c = c;
    }
    __syncthreads();
    if (t < D) {
        float s0 = 0.f, s1 = 0.f;
        #pragma unroll
        for (int j = 0; j < D; ++j) {
            s0 += Wl1[t * D + j] * w2u[j];
            s1 += Wl1[t * D + j] * v[j];
        }
        M0[t] = s0; M1[t] = s1;
    }
    __syncthreads();

    const int n = blockIdx.x * blockDim.x + t;
    const float* row = x0 + (size_t)n * D;
    float p0 = 0.f, p1 = 0.f;
    #pragma unroll
    for (int j = 0; j < D; ++j) {
        const float x = row[j];
        p0 += x * M0[j];
        p1 += x * M1[j];
    }
    g_p[2 * n]     = p0;
    g_p[2 * n + 1] = p1;
}

// ---------------------------------------------------------------------------
// Warp processes EPW edges with hoisted loads (MLP), dedup via match_any.
// PASS=0 (zy): z[e]=Σp[n]; y[n]+=z ; also build incidence bitmask.
// PASS=1 (ta): t[e]=Σy[n]; b[e]=t.1 ; a[n]+=t.0
// ---------------------------------------------------------------------------
#define EPW 4
template<int PASS>
__global__ void k_edge(const int* __restrict__ node_idx) {
    const int wg   = (blockIdx.x * blockDim.x + threadIdx.x) >> 5; // global warp
    const int lane = threadIdx.x & 31;
    const int e0   = wg * EPW;

    int nn[EPW];
    #pragma unroll
    for (int i = 0; i < EPW; ++i)
        nn[i] = node_idx[(e0 + i) * DEG + lane];

    bool keep[EPW];
    #pragma unroll
    for (int i = 0; i < EPW; ++i) {
        const unsigned peers = __match_any_sync(0xffffffffu, nn[i]);
        keep[i] = (peers & ((1u << lane) - 1u)) == 0u;
    }

    const float* src = (PASS == 0) ? g_p : g_y;
    float s0[EPW], s1[EPW];
    #pragma unroll
    for (int i = 0; i < EPW; ++i) {
        float2 pv = make_float2(0.f, 0.f);
        if (keep[i]) pv = *(const float2*)&src[2 * nn[i]];
        s0[i] = pv.x; s1[i] = pv.y;
    }
    #pragma unroll
    for (int o = 16; o > 0; o >>= 1) {
        #pragma unroll
        for (int i = 0; i < EPW; ++i) {
            s0[i] += __shfl_xor_sync(0xffffffffu, s0[i], o);
            s1[i] += __shfl_xor_sync(0xffffffffu, s1[i], o);
        }
    }

    #pragma unroll
    for (int i = 0; i < EPW; ++i) {
        const int e = e0 + i;
        if (PASS == 0) {
            // incidence bitmask (idempotent for duplicates)
            atomicOr(&g_mask[nn[i] * MASK_WORDS_PER_ROW + (e >> 5)], 1u << (e & 31));
            if (keep[i]) {
                atomicAdd(&g_y[2 * nn[i]],     s0[i]);
                atomicAdd(&g_y[2 * nn[i] + 1], s1[i]);
            }
        } else {
            if (lane == 0) g_b[e] = s1[i];
            if (keep[i]) atomicAdd(&g_a[nn[i]], s0[i]);
        }
    }
}

// ---------------------------------------------------------------------------
// Stream the full [N, E] output: out[n][e] = bit(n,e) ? a[n]+b[e]+c : 0.
// grid = (E/1024, N), block = 256, float4 per thread. Write-bandwidth bound.
// ---------------------------------------------------------------------------
__global__ void k_fill(float4* __restrict__ out) {
    const int n  = blockIdx.y;
    const int e0 = blockIdx.x * 1024 + threadIdx.x * 4;
    const unsigned word = g_mask[n * MASK_WORDS_PER_ROW + (e0 >> 5)];
    float4 r = make_float4(0.f, 0.f, 0.f, 0.f);
    if (word) {  // most words are 0: skip b-load + math
        const float ac = g_a[n] + g_c;
        const float4 bv = *(const float4*)&g_b[e0];
        const unsigned sh = e0 & 31;
        if ((word >> (sh + 0)) & 1u) r.x = ac + bv.x;
        if ((word >> (sh + 1)) & 1u) r.y = ac + bv.y;
        if ((word >> (sh + 2)) & 1u) r.z = ac + bv.z;
        if ((word >> (sh + 3)) & 1u) r.w = ac + bv.w;
    }
    out[((size_t)n * N_EDGES + e0) >> 2] = r;
}

extern "C" void kernel_launch(void* const* d_in, const int* in_sizes, int n_in,
                              void* d_out, int out_size) {
    const float* x0   = (const float*)d_in[0];
    // d_in[1] = dense incidence (unused)
    const float* Wl1  = (const float*)d_in[2];
    const float* Wl2  = (const float*)d_in[3];
    const float* Wm1  = (const float*)d_in[4];
    const float* bm1  = (const float*)d_in[5];
    const float* Wm2  = (const float*)d_in[6];
    const float* bm2  = (const float*)d_in[7];
    const float* Wm3  = (const float*)d_in[8];
    const float* bm3  = (const float*)d_in[9];
    const int*   nidx = (const int*)d_in[10];
    // d_in[11] = edge_idx (implied: e = i >> 5)

    float4* out = (float4*)d_out;

    k_init<<<(MASK_WORDS / 4 + 255) / 256, 256>>>();
    k_p<<<N_NODES / 256, 256>>>(x0, Wl1, Wl2, Wm1, bm1, Wm2, bm2, Wm3, bm3);
    k_edge<0><<<N_EDGES / (8 * EPW), 256>>>(nidx);   // zy + mask build
    k_edge<1><<<N_EDGES / (8 * EPW), 256>>>(nidx);   // ta -> a, b
    {
        dim3 grid(N_EDGES / 1024, N_NODES);
        k_fill<<<grid, 256>>>(out);
    }
}

// round 4
// speedup vs baseline: 1.2448x; 1.2448x over previous
#include <cuda_runtime.h>
#include <cstdint>

#define NN   8192
#define NE   8192
#define DEG  32
#define NNZC (NE * DEG)
#define D    32

// ---- device scratch (no allocations allowed) ----
__device__ float  g_c;
__device__ float2 g_p[NN];      // p[n] = x_0[n] @ M
__device__ float2 g_y[NN];      // y[n] = sum_{e∋n} z[e]
__device__ float  g_a[NN];      // a[n] = sum_{e∋n} t[e].0
__device__ float  g_b[NE];      // b[e] = t[e].1
__device__ unsigned g_ticket;       // zero-fill chunk queue (reset at kernel end)
__device__ unsigned g_bar_count[2]; // [0]=chain, [1]=global
__device__ unsigned g_bar_gen[2];

// Sense-free generation barrier (safe across graph replays: gen only grows).
__device__ __forceinline__ void dev_barrier(int slot, unsigned expected) {
    __syncthreads();
    if (threadIdx.x == 0) {
        volatile unsigned* genp = (volatile unsigned*)&g_bar_gen[slot];
        const unsigned g = *genp;
        __threadfence();
        if (atomicAdd(&g_bar_count[slot], 1u) == expected - 1u) {
            g_bar_count[slot] = 0u;
            __threadfence();
            atomicAdd(&g_bar_gen[slot], 1u);
        } else {
            while (*genp == g) __nanosleep(64);
            __threadfence();
        }
    }
    __syncthreads();
}

// Warp-level: dedup-gather-sum of src over one edge, return (s0,s1) on all lanes.
__device__ __forceinline__ void edge_reduce(const int* __restrict__ nidx, int e,
                                            const float2* __restrict__ src,
                                            int lane, unsigned lt,
                                            int& n, bool& keep, float& s0, float& s1) {
    n = nidx[e * DEG + lane];
    const unsigned peers = __match_any_sync(0xffffffffu, n);
    keep = (peers & lt) == 0u;
    s0 = 0.f; s1 = 0.f;
    if (keep) { const float2 pv = src[n]; s0 = pv.x; s1 = pv.y; }
    #pragma unroll
    for (int o = 16; o > 0; o >>= 1) {
        s0 += __shfl_xor_sync(0xffffffffu, s0, o);
        s1 += __shfl_xor_sync(0xffffffffu, s1, o);
    }
}

__global__ void __launch_bounds__(256, 4)
k_all(const float* __restrict__ x0,
      const float* __restrict__ Wl1, const float* __restrict__ Wl2,
      const float* __restrict__ Wm1, const float* __restrict__ bm1,
      const float* __restrict__ Wm2, const float* __restrict__ bm2,
      const float* __restrict__ Wm3, const float* __restrict__ bm3,
      const int* __restrict__ nidx, float* __restrict__ out, int CB) {
    const int t   = threadIdx.x;
    const int bid = blockIdx.x;

    if (bid < CB) {
        // ---------- fold affine chain into M (32x2) + c (redundant per block) ----
        __shared__ float q[D], u[D], v[D], w2u[D], M0[D], M1[D];
        if (t < D) {
            float s = 0.f;
            #pragma unroll
            for (int j = 0; j < D; ++j) s += Wm2[t * D + j] * Wm3[j];
            q[t] = s;
        }
        __syncthreads();
        if (t < D) {
            float su = 0.f, sv = 0.f;
            #pragma unroll
            for (int j = 0; j < D; ++j) {
                su += Wm1[t * D + j] * q[j];
                sv += Wm1[(D + t) * D + j] * q[j];
            }
            u[t] = su; v[t] = sv;
        }
        __syncthreads();
        if (t < D) {
            float s = 0.f;
            #pragma unroll
            for (int j = 0; j < D; ++j) s += Wl2[t * D + j] * u[j];
            w2u[t] = s;
        }
        if (bid == 0 && t == 0) {
            float c = bm3[0];
            #pragma unroll
            for (int j = 0; j < D; ++j) c += bm1[j] * q[j] + bm2[j] * Wm3[j];
            g_c = c;
        }
        __syncthreads();
        if (t < D) {
            float s0 = 0.f, s1 = 0.f;
            #pragma unroll
            for (int j = 0; j < D; ++j) {
                s0 += Wl1[t * D + j] * w2u[j];
                s1 += Wl1[t * D + j] * v[j];
            }
            M0[t] = s0; M1[t] = s1;
        }
        __syncthreads();

        // ---------- p[n] = x0[n] @ M ; zero y, a -------------------------------
        for (int n = bid * 256 + t; n < NN; n += CB * 256) {
            const float4* row = (const float4*)(x0 + (size_t)n * D);
            float p0 = 0.f, p1 = 0.f;
            #pragma unroll
            for (int j = 0; j < 8; ++j) {
                const float4 xv = row[j];
                p0 += xv.x * M0[4*j] + xv.y * M0[4*j+1] + xv.z * M0[4*j+2] + xv.w * M0[4*j+3];
                p1 += xv.x * M1[4*j] + xv.y * M1[4*j+1] + xv.z * M1[4*j+2] + xv.w * M1[4*j+3];
            }
            g_p[n] = make_float2(p0, p1);
            g_y[n] = make_float2(0.f, 0.f);
            g_a[n] = 0.f;
        }
        dev_barrier(0, (unsigned)CB);

        // ---------- zy: z[e] = Σ p[n∈e] ; y[n] += z[e] -------------------------
        const int lane = t & 31;
        const unsigned lt = (1u << lane) - 1u;
        const int CW = CB * 8;  // chain warps
        for (int e = bid * 8 + (t >> 5); e < NE; e += CW) {
            int n; bool keep; float s0, s1;
            edge_reduce(nidx, e, g_p, lane, lt, n, keep, s0, s1);
            if (keep) {
                atomicAdd(&g_y[n].x, s0);
                atomicAdd(&g_y[n].y, s1);
            }
        }
        dev_barrier(0, (unsigned)CB);

        // ---------- ta: t[e] = Σ y[n∈e] ; b[e] = t.1 ; a[n] += t.0 -------------
        for (int e = bid * 8 + (t >> 5); e < NE; e += CW) {
            int n; bool keep; float s0, s1;
            edge_reduce(nidx, e, g_y, lane, lt, n, keep, s0, s1);
            if (lane == 0) g_b[e] = s1;
            if (keep) atomicAdd(&g_a[n], s0);
        }
        // a, b published by the global barrier below.
    }

    // ---------- zero-fill output via ticket queue (all blocks) ------------------
    {
        const float4 z4 = make_float4(0.f, 0.f, 0.f, 0.f);
        float4* out4 = (float4*)out;
        const int CHUNK4 = 8192;                         // 128 KB per chunk
        const int NCHUNK = (int)(((size_t)NN * NE / 4) / CHUNK4);  // 2048
        __shared__ unsigned s_ticket;
        for (;;) {
            __syncthreads();
            if (t == 0) s_ticket = atomicAdd(&g_ticket, 1u);
            __syncthreads();
            const unsigned c = s_ticket;
            if (c >= (unsigned)NCHUNK) break;
            float4* dst = out4 + (size_t)c * CHUNK4;
            #pragma unroll 4
            for (int i = t; i < CHUNK4; i += 256) dst[i] = z4;
        }
    }

    dev_barrier(1, gridDim.x);

    // ---------- scatter vals at nnz positions (duplicates write same value) ----
    {
        const float cc = g_c;
        for (int i = bid * 256 + t; i < NNZC; i += gridDim.x * 256) {
            const int n = nidx[i];
            const int e = i >> 5;   // edge_idx = repeat(arange(E), DEG)
            out[(size_t)n * NE + e] = g_a[n] + g_b[e] + cc;
        }
    }

    // reset ticket for the next (graph-replayed) launch
    if (bid == 0 && t == 0) g_ticket = 0u;
}

extern "C" void kernel_launch(void* const* d_in, const int* in_sizes, int n_in,
                              void* d_out, int out_size) {
    const float* x0   = (const float*)d_in[0];
    // d_in[1] = dense incidence (unused)
    const float* Wl1  = (const float*)d_in[2];
    const float* Wl2  = (const float*)d_in[3];
    const float* Wm1  = (const float*)d_in[4];
    const float* bm1  = (const float*)d_in[5];
    const float* Wm2  = (const float*)d_in[6];
    const float* bm2  = (const float*)d_in[7];
    const float* Wm3  = (const float*)d_in[8];
    const float* bm3  = (const float*)d_in[9];
    const int*   nidx = (const int*)d_in[10];
    // d_in[11] = edge_idx (implied: e = i >> 5)

    // Size the grid so every block is co-resident (software barriers need it).
    int dev = 0;
    cudaGetDevice(&dev);
    int sms = 0;
    cudaDeviceGetAttribute(&sms, cudaDevAttrMultiProcessorCount, dev);
    int nb = 0;
    cudaOccupancyMaxActiveBlocksPerMultiprocessor(&nb, k_all, 256, 0);
    if (sms <= 0) sms = 148;
    if (nb  <= 0) nb  = 4;
    int grid = sms * nb;
    if (grid > 2048) grid = 2048;
    int cb = grid / 2 < 128 ? grid / 2 : 128;

    k_all<<<grid, 256>>>(x0, Wl1, Wl2, Wm1, bm1, Wm2, bm2, Wm3, bm3,
                         nidx, (float*)d_out, cb);
}